// round 1
// baseline (speedup 1.0000x reference)
#include <cuda_runtime.h>
#include <cstdint>
#include <cstddef>

#define BB 128
#define TT 128
#define HH 1024
#define H3 3072

// Scratch (static device globals -- no dynamic allocation allowed).
__device__ float g_xp[50331648ULL];      // [T][B][3H] = 128*128*3072 (192 MB)
__device__ float g_hbuf[2 * BB * HH];    // double-buffered hidden state

__device__ __forceinline__ uint32_t f2tf(float f) {
    uint32_t u;
    asm("cvt.rna.tf32.f32 %0, %1;" : "=r"(u) : "f"(f));
    return u;
}

__device__ __forceinline__ void mma_tf32(float d[4], const uint32_t a[4], const uint32_t b[2]) {
    asm volatile(
        "mma.sync.aligned.m16n8k8.row.col.f32.tf32.tf32.f32 "
        "{%0,%1,%2,%3}, {%4,%5,%6,%7}, {%8,%9}, {%0,%1,%2,%3};"
        : "+f"(d[0]), "+f"(d[1]), "+f"(d[2]), "+f"(d[3])
        : "r"(a[0]), "r"(a[1]), "r"(a[2]), "r"(a[3]), "r"(b[0]), "r"(b[1]));
}

// ---------------------------------------------------------------------------
// xproj: C[m][n] = sum_k A[m][k] * W[n][k] + bias[n]
//   m = t*B + b, A row taken from cur[(b*T + t)*H], output xp[m*3H + n].
//   BM=BN=128, BK=16, 256 threads, 8 warps (2m x 4n), warp tile 64x32.
// ---------------------------------------------------------------------------
#define XST 20  // BK(16) + 4 pad -> conflict-free fragment loads

__global__ __launch_bounds__(256) void xproj_kernel(
    const float* __restrict__ cur, const float* __restrict__ W,
    const float* __restrict__ bias, float* __restrict__ xp)
{
    __shared__ uint32_t As[2][128 * XST];
    __shared__ uint32_t Bs[2][128 * XST];

    const int tid  = threadIdx.x;
    const int lane = tid & 31;
    const int wid  = tid >> 5;
    const int wm   = (wid >> 2) * 64;
    const int wn   = (wid & 3) * 32;
    const int m0   = blockIdx.y * 128;
    const int n0   = blockIdx.x * 128;

    // Global-load mapping: A tile 128x16 = 512 float4, B tile same; 2+2 per thread.
    const float* gp[4];
    int soff[2];
    #pragma unroll
    for (int i = 0; i < 2; i++) {
        int idx = tid + i * 256;
        int row = idx >> 2, kv = idx & 3;
        int m = m0 + row;
        int b = m & (BB - 1);
        int t = m >> 7;
        gp[i]     = cur + ((size_t)b * TT + t) * HH + kv * 4;
        gp[2 + i] = W + (size_t)(n0 + row) * HH + kv * 4;
        soff[i]   = row * XST + kv * 4;
    }

    float acc[4][4][4];
    #pragma unroll
    for (int a = 0; a < 4; a++)
        #pragma unroll
        for (int b = 0; b < 4; b++)
            #pragma unroll
            for (int c = 0; c < 4; c++) acc[a][b][c] = 0.f;

    float4 rv[4];
    #pragma unroll
    for (int i = 0; i < 4; i++) rv[i] = *(const float4*)(gp[i]);
    #pragma unroll
    for (int i = 0; i < 2; i++) {
        uint32_t* p = &As[0][soff[i]];
        p[0] = f2tf(rv[i].x); p[1] = f2tf(rv[i].y); p[2] = f2tf(rv[i].z); p[3] = f2tf(rv[i].w);
        uint32_t* q = &Bs[0][soff[i]];
        q[0] = f2tf(rv[2+i].x); q[1] = f2tf(rv[2+i].y); q[2] = f2tf(rv[2+i].z); q[3] = f2tf(rv[2+i].w);
    }
    __syncthreads();

    const int NKT = HH / 16;  // 64
    for (int kt = 0; kt < NKT; kt++) {
        int cb = kt & 1;
        if (kt + 1 < NKT) {
            #pragma unroll
            for (int i = 0; i < 4; i++)
                rv[i] = *(const float4*)(gp[i] + (kt + 1) * 16);
        }
        #pragma unroll
        for (int kk = 0; kk < 2; kk++) {
            uint32_t af[4][4], bf[4][2];
            const int c  = kk * 8 + (lane & 3);
            const int rA = wm + (lane >> 2);
            #pragma unroll
            for (int mt = 0; mt < 4; mt++) {
                int r = rA + mt * 16;
                af[mt][0] = As[cb][r * XST + c];
                af[mt][1] = As[cb][(r + 8) * XST + c];
                af[mt][2] = As[cb][r * XST + c + 4];
                af[mt][3] = As[cb][(r + 8) * XST + c + 4];
            }
            const int rB = wn + (lane >> 2);
            #pragma unroll
            for (int nt = 0; nt < 4; nt++) {
                int r = rB + nt * 8;
                bf[nt][0] = Bs[cb][r * XST + c];
                bf[nt][1] = Bs[cb][r * XST + c + 4];
            }
            #pragma unroll
            for (int mt = 0; mt < 4; mt++)
                #pragma unroll
                for (int nt = 0; nt < 4; nt++)
                    mma_tf32(acc[mt][nt], af[mt], bf[nt]);
        }
        if (kt + 1 < NKT) {
            int nb = cb ^ 1;
            #pragma unroll
            for (int i = 0; i < 2; i++) {
                uint32_t* p = &As[nb][soff[i]];
                p[0] = f2tf(rv[i].x); p[1] = f2tf(rv[i].y); p[2] = f2tf(rv[i].z); p[3] = f2tf(rv[i].w);
                uint32_t* q = &Bs[nb][soff[i]];
                q[0] = f2tf(rv[2+i].x); q[1] = f2tf(rv[2+i].y); q[2] = f2tf(rv[2+i].z); q[3] = f2tf(rv[2+i].w);
            }
            __syncthreads();
        }
    }

    // Epilogue: +bias, coalesced row-major store into xp.
    #pragma unroll
    for (int mt = 0; mt < 4; mt++) {
        int r = m0 + wm + mt * 16 + (lane >> 2);
        #pragma unroll
        for (int nt = 0; nt < 4; nt++) {
            int cg = n0 + wn + nt * 8 + (lane & 3) * 2;
            float2 bz = *(const float2*)(bias + cg);
            float2 v0 = make_float2(acc[mt][nt][0] + bz.x, acc[mt][nt][1] + bz.y);
            float2 v1 = make_float2(acc[mt][nt][2] + bz.x, acc[mt][nt][3] + bz.y);
            *(float2*)(xp + (size_t)r * H3 + cg)       = v0;
            *(float2*)(xp + (size_t)(r + 8) * H3 + cg) = v1;
        }
    }
}

// ---------------------------------------------------------------------------
// step: one GRU timestep.
//   CTA tile: 32 batches x 32 hidden units x 3 gates (96 GEMM cols), K=1024.
//   Grid (32, 4) = 128 CTAs. 256 threads, 8 warps (2m x 4n), warp 16x24.
//   GEMM accumulators round-trip through SMEM so gate fusion sees all 3 gates.
// ---------------------------------------------------------------------------
#define SST 20

__global__ __launch_bounds__(256) void step_kernel(
    const float* __restrict__ hprev, const float* __restrict__ Wh,
    const float* __restrict__ bhv, const float* __restrict__ xp_t,
    float* __restrict__ hnext, float* __restrict__ y, int t)
{
    __shared__ uint32_t sm[2][128 * SST];  // per buffer: rows 0..31 A(h), rows 32..127 B(Wh)

    const int tid  = threadIdx.x;
    const int lane = tid & 31;
    const int wid  = tid >> 5;
    const int o0   = blockIdx.x * 32;
    const int b0   = blockIdx.y * 32;
    const int wm   = (wid >> 2) * 16;
    const int wn   = (wid & 3) * 24;

    // Global-load mapping: 512 float4 total (128 A + 384 B) -> 2 per thread.
    const float* gp[2];
    int soff[2];
    #pragma unroll
    for (int i = 0; i < 2; i++) {
        int idx = tid + i * 256;
        if (idx < 128) {
            int row = idx >> 2, kv = idx & 3;
            gp[i]   = hprev + (size_t)(b0 + row) * HH + kv * 4;
            soff[i] = row * SST + kv * 4;
        } else {
            int j = idx - 128;
            int row = j >> 2, kv = j & 3;  // row 0..95 packed as gate*32 + o
            gp[i]   = Wh + ((size_t)(row >> 5) * HH + o0 + (row & 31)) * HH + kv * 4;
            soff[i] = (32 + row) * SST + kv * 4;
        }
    }

    float acc[3][4];
    #pragma unroll
    for (int nt = 0; nt < 3; nt++)
        #pragma unroll
        for (int c = 0; c < 4; c++) acc[nt][c] = 0.f;

    float4 rv[2];
    #pragma unroll
    for (int i = 0; i < 2; i++) rv[i] = *(const float4*)(gp[i]);
    #pragma unroll
    for (int i = 0; i < 2; i++) {
        uint32_t* p = &sm[0][soff[i]];
        p[0] = f2tf(rv[i].x); p[1] = f2tf(rv[i].y); p[2] = f2tf(rv[i].z); p[3] = f2tf(rv[i].w);
    }
    __syncthreads();

    const int NKT = HH / 16;  // 64
    for (int kt = 0; kt < NKT; kt++) {
        int cb = kt & 1;
        if (kt + 1 < NKT) {
            #pragma unroll
            for (int i = 0; i < 2; i++)
                rv[i] = *(const float4*)(gp[i] + (kt + 1) * 16);
        }
        #pragma unroll
        for (int kk = 0; kk < 2; kk++) {
            const uint32_t* S = sm[cb];
            uint32_t af[4], bf[3][2];
            const int c = kk * 8 + (lane & 3);
            const int r = wm + (lane >> 2);
            af[0] = S[r * SST + c];
            af[1] = S[(r + 8) * SST + c];
            af[2] = S[r * SST + c + 4];
            af[3] = S[(r + 8) * SST + c + 4];
            #pragma unroll
            for (int nt = 0; nt < 3; nt++) {
                int br = 32 + wn + nt * 8 + (lane >> 2);
                bf[nt][0] = S[br * SST + c];
                bf[nt][1] = S[br * SST + c + 4];
            }
            #pragma unroll
            for (int nt = 0; nt < 3; nt++)
                mma_tf32(acc[nt], af, bf[nt]);
        }
        if (kt + 1 < NKT) {
            int nb = cb ^ 1;
            #pragma unroll
            for (int i = 0; i < 2; i++) {
                uint32_t* p = &sm[nb][soff[i]];
                p[0] = f2tf(rv[i].x); p[1] = f2tf(rv[i].y); p[2] = f2tf(rv[i].z); p[3] = f2tf(rv[i].w);
            }
            __syncthreads();
        }
    }
    __syncthreads();  // all mma fragment reads done -> safe to alias smem

    // Scatter accumulators to SMEM: Cs[32][100] (fp32), aliased onto sm.
    float* Cs = (float*)sm;
    #pragma unroll
    for (int nt = 0; nt < 3; nt++) {
        int r = wm + (lane >> 2);
        int c = wn + nt * 8 + (lane & 3) * 2;
        Cs[r * 100 + c]           = acc[nt][0];
        Cs[r * 100 + c + 1]       = acc[nt][1];
        Cs[(r + 8) * 100 + c]     = acc[nt][2];
        Cs[(r + 8) * 100 + c + 1] = acc[nt][3];
    }
    __syncthreads();

    // Gate fusion: 1024 outputs / 256 threads = 4 each (4 consecutive units).
    const int b  = tid >> 3;
    const int oq = (tid & 7) * 4;
    const int bg = b0 + b;
    const float* xpr = xp_t + (size_t)bg * H3;
    #pragma unroll
    for (int j = 0; j < 4; j++) {
        int o  = oq + j;
        int og = o0 + o;
        float hr = Cs[b * 100 + o]      + bhv[og];
        float hz = Cs[b * 100 + 32 + o] + bhv[HH + og];
        float hn = Cs[b * 100 + 64 + o] + bhv[2 * HH + og];
        float xr = xpr[og];
        float xz = xpr[HH + og];
        float xn = xpr[2 * HH + og];
        float r  = 1.f / (1.f + __expf(-(xr + hr)));
        float z  = 1.f / (1.f + __expf(-(xz + hz)));
        float n  = tanhf(xn + r * hn);
        float hp = hprev[(size_t)bg * HH + og];
        float hv = (1.f - z) * n + z * hp;
        hnext[(size_t)bg * HH + og]            = hv;
        y[((size_t)bg * TT + t) * HH + og]     = hv;
    }
}

// ---------------------------------------------------------------------------
extern "C" void kernel_launch(void* const* d_in, const int* in_sizes, int n_in,
                              void* d_out, int out_size)
{
    (void)in_sizes; (void)n_in; (void)out_size;
    const float* x   = (const float*)d_in[0];  // [B,T,H]
    const float* h0  = (const float*)d_in[1];  // [L,B,H]
    const float* Wx  = (const float*)d_in[2];  // [L,3,H,H]
    const float* Wh  = (const float*)d_in[3];  // [L,3,H,H]
    const float* bx  = (const float*)d_in[4];  // [L,3,H]
    const float* bh  = (const float*)d_in[5];  // [L,3,H]
    float* out   = (float*)d_out;                     // [B,T,H] then [L,B,H]
    float* hlast = out + (size_t)BB * TT * HH;

    float* xp   = nullptr;
    float* hbuf = nullptr;
    cudaGetSymbolAddress((void**)&xp, g_xp);
    cudaGetSymbolAddress((void**)&hbuf, g_hbuf);
    float* hA = hbuf;
    float* hB = hbuf + BB * HH;

    dim3 xgrid(H3 / 128, (BB * TT) / 128);  // (24, 128)
    dim3 sgrid(HH / 32, BB / 32);           // (32, 4)

    for (int l = 0; l < 2; l++) {
        const float* cur = (l == 0) ? x : out;  // layer-1 input = layer-0 output
        xproj_kernel<<<xgrid, 256>>>(cur, Wx + (size_t)l * 3 * HH * HH,
                                     bx + (size_t)l * 3 * HH, xp);
        cudaMemcpyAsync(hA, h0 + (size_t)l * BB * HH, (size_t)BB * HH * sizeof(float),
                        cudaMemcpyDeviceToDevice);
        for (int t = 0; t < TT; t++) {
            const float* hp = (t & 1) ? hB : hA;
            float*       hn = (t & 1) ? hA : hB;
            step_kernel<<<sgrid, 256>>>(hp, Wh + (size_t)l * 3 * HH * HH,
                                        bh + (size_t)l * 3 * HH,
                                        xp + (size_t)t * BB * H3, hn, out, t);
        }
        // T=128 even -> final hidden ends up in hA
        cudaMemcpyAsync(hlast + (size_t)l * BB * HH, hA, (size_t)BB * HH * sizeof(float),
                        cudaMemcpyDeviceToDevice);
    }
}

// round 2
// speedup vs baseline: 1.6660x; 1.6660x over previous
#include <cuda_runtime.h>
#include <cstdint>
#include <cstddef>

#define BB 128
#define TT 128
#define HH 1024
#define H3 3072

// Scratch (static device globals -- no dynamic allocation allowed).
__device__ float    g_xp[50331648ULL];         // [T][B][3H] fp32 (192 MB)
__device__ uint32_t g_whtf[2ULL * 3 * HH * HH]; // Wh pre-converted to tf32 (25 MB)
__device__ float    g_hbuf[2 * BB * HH];        // double-buffered h (fp32)
__device__ uint32_t g_htf[2 * BB * HH];         // double-buffered h (tf32)

__device__ __forceinline__ uint32_t f2tf(float f) {
    uint32_t u;
    asm("cvt.rna.tf32.f32 %0, %1;" : "=r"(u) : "f"(f));
    return u;
}

__device__ __forceinline__ void mma_tf32(float d[4], const uint32_t a[4], const uint32_t b[2]) {
    asm volatile(
        "mma.sync.aligned.m16n8k8.row.col.f32.tf32.tf32.f32 "
        "{%0,%1,%2,%3}, {%4,%5,%6,%7}, {%8,%9}, {%0,%1,%2,%3};"
        : "+f"(d[0]), "+f"(d[1]), "+f"(d[2]), "+f"(d[3])
        : "r"(a[0]), "r"(a[1]), "r"(a[2]), "r"(a[3]), "r"(b[0]), "r"(b[1]));
}

__device__ __forceinline__ void ldsm4(uint32_t& r0, uint32_t& r1, uint32_t& r2, uint32_t& r3,
                                      uint32_t addr) {
    asm volatile("ldmatrix.sync.aligned.m8n8.x4.shared.b16 {%0,%1,%2,%3}, [%4];"
                 : "=r"(r0), "=r"(r1), "=r"(r2), "=r"(r3) : "r"(addr));
}
__device__ __forceinline__ void ldsm2(uint32_t& r0, uint32_t& r1, uint32_t addr) {
    asm volatile("ldmatrix.sync.aligned.m8n8.x2.shared.b16 {%0,%1}, [%2];"
                 : "=r"(r0), "=r"(r1) : "r"(addr));
}

// ---------------------------------------------------------------------------
// Elementwise fp32 -> tf32 conversion (vectorized x4).
// ---------------------------------------------------------------------------
__global__ void cvt_tf32_kernel(const float* __restrict__ src, uint32_t* __restrict__ dst, int n4)
{
    int i = blockIdx.x * blockDim.x + threadIdx.x;
    if (i < n4) {
        float4 v = ((const float4*)src)[i];
        uint4 o;
        o.x = f2tf(v.x); o.y = f2tf(v.y); o.z = f2tf(v.z); o.w = f2tf(v.w);
        ((uint4*)dst)[i] = o;
    }
}

// ---------------------------------------------------------------------------
// xproj: C[m][n] = sum_k A[m][k] * W[n][k] + bias[n]   (unchanged from R1)
// ---------------------------------------------------------------------------
#define XST 20

__global__ __launch_bounds__(256) void xproj_kernel(
    const float* __restrict__ cur, const float* __restrict__ W,
    const float* __restrict__ bias, float* __restrict__ xp)
{
    __shared__ uint32_t As[2][128 * XST];
    __shared__ uint32_t Bs[2][128 * XST];

    const int tid  = threadIdx.x;
    const int lane = tid & 31;
    const int wid  = tid >> 5;
    const int wm   = (wid >> 2) * 64;
    const int wn   = (wid & 3) * 32;
    const int m0   = blockIdx.y * 128;
    const int n0   = blockIdx.x * 128;

    const float* gp[4];
    int soff[2];
    #pragma unroll
    for (int i = 0; i < 2; i++) {
        int idx = tid + i * 256;
        int row = idx >> 2, kv = idx & 3;
        int m = m0 + row;
        int b = m & (BB - 1);
        int t = m >> 7;
        gp[i]     = cur + ((size_t)b * TT + t) * HH + kv * 4;
        gp[2 + i] = W + (size_t)(n0 + row) * HH + kv * 4;
        soff[i]   = row * XST + kv * 4;
    }

    float acc[4][4][4];
    #pragma unroll
    for (int a = 0; a < 4; a++)
        #pragma unroll
        for (int b = 0; b < 4; b++)
            #pragma unroll
            for (int c = 0; c < 4; c++) acc[a][b][c] = 0.f;

    float4 rv[4];
    #pragma unroll
    for (int i = 0; i < 4; i++) rv[i] = *(const float4*)(gp[i]);
    #pragma unroll
    for (int i = 0; i < 2; i++) {
        uint32_t* p = &As[0][soff[i]];
        p[0] = f2tf(rv[i].x); p[1] = f2tf(rv[i].y); p[2] = f2tf(rv[i].z); p[3] = f2tf(rv[i].w);
        uint32_t* q = &Bs[0][soff[i]];
        q[0] = f2tf(rv[2+i].x); q[1] = f2tf(rv[2+i].y); q[2] = f2tf(rv[2+i].z); q[3] = f2tf(rv[2+i].w);
    }
    __syncthreads();

    const int NKT = HH / 16;
    for (int kt = 0; kt < NKT; kt++) {
        int cb = kt & 1;
        if (kt + 1 < NKT) {
            #pragma unroll
            for (int i = 0; i < 4; i++)
                rv[i] = *(const float4*)(gp[i] + (kt + 1) * 16);
        }
        #pragma unroll
        for (int kk = 0; kk < 2; kk++) {
            uint32_t af[4][4], bf[4][2];
            const int c  = kk * 8 + (lane & 3);
            const int rA = wm + (lane >> 2);
            #pragma unroll
            for (int mt = 0; mt < 4; mt++) {
                int r = rA + mt * 16;
                af[mt][0] = As[cb][r * XST + c];
                af[mt][1] = As[cb][(r + 8) * XST + c];
                af[mt][2] = As[cb][r * XST + c + 4];
                af[mt][3] = As[cb][(r + 8) * XST + c + 4];
            }
            const int rB = wn + (lane >> 2);
            #pragma unroll
            for (int nt = 0; nt < 4; nt++) {
                int r = rB + nt * 8;
                bf[nt][0] = Bs[cb][r * XST + c];
                bf[nt][1] = Bs[cb][r * XST + c + 4];
            }
            #pragma unroll
            for (int mt = 0; mt < 4; mt++)
                #pragma unroll
                for (int nt = 0; nt < 4; nt++)
                    mma_tf32(acc[mt][nt], af[mt], bf[nt]);
        }
        if (kt + 1 < NKT) {
            int nb = cb ^ 1;
            #pragma unroll
            for (int i = 0; i < 2; i++) {
                uint32_t* p = &As[nb][soff[i]];
                p[0] = f2tf(rv[i].x); p[1] = f2tf(rv[i].y); p[2] = f2tf(rv[i].z); p[3] = f2tf(rv[i].w);
                uint32_t* q = &Bs[nb][soff[i]];
                q[0] = f2tf(rv[2+i].x); q[1] = f2tf(rv[2+i].y); q[2] = f2tf(rv[2+i].z); q[3] = f2tf(rv[2+i].w);
            }
            __syncthreads();
        }
    }

    #pragma unroll
    for (int mt = 0; mt < 4; mt++) {
        int r = m0 + wm + mt * 16 + (lane >> 2);
        #pragma unroll
        for (int nt = 0; nt < 4; nt++) {
            int cg = n0 + wn + nt * 8 + (lane & 3) * 2;
            float2 bz = *(const float2*)(bias + cg);
            float2 v0 = make_float2(acc[mt][nt][0] + bz.x, acc[mt][nt][1] + bz.y);
            float2 v1 = make_float2(acc[mt][nt][2] + bz.x, acc[mt][nt][3] + bz.y);
            *(float2*)(xp + (size_t)r * H3 + cg)       = v0;
            *(float2*)(xp + (size_t)(r + 8) * H3 + cg) = v1;
        }
    }
}

// ---------------------------------------------------------------------------
// step v2: 4-stage cp.async pipeline + ldmatrix fragment loads, zero cvt in
// the mainloop (operands pre-converted to tf32).
//   CTA: 32 batches x 96 GEMM cols (3 gates x 32 units), K=1024, 8 warps.
// ---------------------------------------------------------------------------
#define NST   4
#define ROWST 20                 // u32 per smem row (16 + 4 pad -> LDSM conflict-free)
#define STG   (128 * ROWST)      // u32 per stage (rows 0..31 A, 32..127 B)

__global__ __launch_bounds__(256) void step2_kernel(
    const float*    __restrict__ hprev,     // fp32 [B,H]  (for z*h and outputs)
    const uint32_t* __restrict__ hprev_tf,  // tf32 [B,H]
    const uint32_t* __restrict__ Wh_tf,     // tf32 [3,H,H]
    const float*    __restrict__ bhv,       // [3,H]
    const float*    __restrict__ xp_t,      // [B,3H]
    float* __restrict__ hnext, uint32_t* __restrict__ hnext_tf,
    float* __restrict__ y, int t)
{
    __shared__ uint32_t sm[NST][STG];       // 40 KB

    const int tid  = threadIdx.x;
    const int lane = tid & 31;
    const int wid  = tid >> 5;
    const int o0   = blockIdx.x * 32;
    const int b0   = blockIdx.y * 32;
    const int wm   = (wid >> 2) * 16;
    const int wn   = (wid & 3) * 24;

    uint32_t smbase;
    asm("{.reg .u64 tt; cvta.to.shared.u64 tt, %1; cvt.u32.u64 %0, tt;}"
        : "=r"(smbase) : "l"(&sm[0][0]));

    // cp.async mapping: 512 x 16B chunks per stage, 2 per thread.
    const uint32_t* gsrc[2];
    uint32_t sdst[2];
    #pragma unroll
    for (int i = 0; i < 2; i++) {
        int idx = tid + i * 256;
        if (idx < 128) {
            int row = idx >> 2, kv = idx & 3;
            gsrc[i] = hprev_tf + (size_t)(b0 + row) * HH + kv * 4;
            sdst[i] = (uint32_t)(row * ROWST + kv * 4) * 4;
        } else {
            int j = idx - 128;
            int row = j >> 2, kv = j & 3;          // row 0..95 = gate*32 + o_local
            gsrc[i] = Wh_tf + ((size_t)(row >> 5) * HH + o0 + (row & 31)) * HH + kv * 4;
            sdst[i] = (uint32_t)((32 + row) * ROWST + kv * 4) * 4;
        }
    }

    // Prologue: fill 3 stages.
    #pragma unroll
    for (int s = 0; s < 3; s++) {
        #pragma unroll
        for (int i = 0; i < 2; i++) {
            uint32_t sa = smbase + (uint32_t)s * (STG * 4) + sdst[i];
            const void* ga = gsrc[i] + s * 16;
            asm volatile("cp.async.cg.shared.global [%0], [%1], 16;" :: "r"(sa), "l"(ga));
        }
        asm volatile("cp.async.commit_group;");
    }

    float acc[3][4];
    #pragma unroll
    for (int nt = 0; nt < 3; nt++)
        #pragma unroll
        for (int c = 0; c < 4; c++) acc[nt][c] = 0.f;

    // Invariant ldmatrix address components (per-lane).
    const int g  = lane >> 3;
    const int r8 = lane & 7;
    const uint32_t aoff  = (uint32_t)((wm + (g & 1) * 8 + r8) * ROWST + (g >> 1) * 4) * 4;
    const uint32_t b1off = (uint32_t)((32 + wn + (g >> 1) * 8 + r8) * ROWST + (g & 1) * 4) * 4;
    const uint32_t b2off = (uint32_t)((32 + wn + 16 + r8) * ROWST + (g & 1) * 4) * 4;

    const int NKT = HH / 16;  // 64
    for (int kt = 0; kt < NKT; kt++) {
        asm volatile("cp.async.wait_group 2;");
        __syncthreads();
        uint32_t sb = smbase + (uint32_t)(kt & (NST - 1)) * (STG * 4);
        #pragma unroll
        for (int kk = 0; kk < 2; kk++) {
            uint32_t kb = (uint32_t)kk * 32;   // 8 tf32 * 4B
            uint32_t af[4], bA[4], bB[2];
            ldsm4(af[0], af[1], af[2], af[3], sb + aoff + kb);
            ldsm4(bA[0], bA[1], bA[2], bA[3], sb + b1off + kb);
            ldsm2(bB[0], bB[1],               sb + b2off + kb);
            mma_tf32(acc[0], af, &bA[0]);
            mma_tf32(acc[1], af, &bA[2]);
            mma_tf32(acc[2], af, bB);
        }
        if (kt + 3 < NKT) {
            uint32_t st = (uint32_t)((kt + 3) & (NST - 1));
            #pragma unroll
            for (int i = 0; i < 2; i++) {
                uint32_t sa = smbase + st * (STG * 4) + sdst[i];
                const void* ga = gsrc[i] + (kt + 3) * 16;
                asm volatile("cp.async.cg.shared.global [%0], [%1], 16;" :: "r"(sa), "l"(ga));
            }
        }
        asm volatile("cp.async.commit_group;");
    }
    __syncthreads();  // fragment reads done -> safe to alias smem

    // Scatter accumulators: Cs[32][100] fp32, aliased onto sm.
    float* Cs = (float*)sm;
    #pragma unroll
    for (int nt = 0; nt < 3; nt++) {
        int r = wm + (lane >> 2);
        int c = wn + nt * 8 + (lane & 3) * 2;
        Cs[r * 100 + c]           = acc[nt][0];
        Cs[r * 100 + c + 1]       = acc[nt][1];
        Cs[(r + 8) * 100 + c]     = acc[nt][2];
        Cs[(r + 8) * 100 + c + 1] = acc[nt][3];
    }
    __syncthreads();

    // Gate fusion: thread -> (batch b, 4 consecutive units oq..oq+3).
    const int b  = tid >> 3;
    const int oq = (tid & 7) * 4;
    const int bg = b0 + b;
    const int og = o0 + oq;
    const float* xpr = xp_t + (size_t)bg * H3;

    float4 xr4 = *(const float4*)(xpr + og);
    float4 xz4 = *(const float4*)(xpr + HH + og);
    float4 xn4 = *(const float4*)(xpr + 2 * HH + og);
    float4 br4 = *(const float4*)(bhv + og);
    float4 bz4 = *(const float4*)(bhv + HH + og);
    float4 bn4 = *(const float4*)(bhv + 2 * HH + og);
    float4 hp4 = *(const float4*)(hprev + (size_t)bg * HH + og);

    float hv[4];
    #pragma unroll
    for (int j = 0; j < 4; j++) {
        int o = oq + j;
        float hr = Cs[b * 100 + o]      + ((const float*)&br4)[j];
        float hz = Cs[b * 100 + 32 + o] + ((const float*)&bz4)[j];
        float hn = Cs[b * 100 + 64 + o] + ((const float*)&bn4)[j];
        float r  = 1.f / (1.f + __expf(-(((const float*)&xr4)[j] + hr)));
        float z  = 1.f / (1.f + __expf(-(((const float*)&xz4)[j] + hz)));
        float n  = tanhf(((const float*)&xn4)[j] + r * hn);
        hv[j] = (1.f - z) * n + z * ((const float*)&hp4)[j];
    }
    *(float4*)(hnext + (size_t)bg * HH + og) = make_float4(hv[0], hv[1], hv[2], hv[3]);
    *(float4*)(y + ((size_t)bg * TT + t) * HH + og) = make_float4(hv[0], hv[1], hv[2], hv[3]);
    uint4 tf;
    tf.x = f2tf(hv[0]); tf.y = f2tf(hv[1]); tf.z = f2tf(hv[2]); tf.w = f2tf(hv[3]);
    *(uint4*)(hnext_tf + (size_t)bg * HH + og) = tf;
}

// ---------------------------------------------------------------------------
extern "C" void kernel_launch(void* const* d_in, const int* in_sizes, int n_in,
                              void* d_out, int out_size)
{
    (void)in_sizes; (void)n_in; (void)out_size;
    const float* x   = (const float*)d_in[0];  // [B,T,H]
    const float* h0  = (const float*)d_in[1];  // [L,B,H]
    const float* Wx  = (const float*)d_in[2];  // [L,3,H,H]
    const float* Wh  = (const float*)d_in[3];  // [L,3,H,H]
    const float* bx  = (const float*)d_in[4];  // [L,3,H]
    const float* bh  = (const float*)d_in[5];  // [L,3,H]
    float* out   = (float*)d_out;              // [B,T,H] then [L,B,H]
    float* hlast = out + (size_t)BB * TT * HH;

    float*    xp   = nullptr;
    float*    hbuf = nullptr;
    uint32_t* whtf = nullptr;
    uint32_t* htf  = nullptr;
    cudaGetSymbolAddress((void**)&xp,   g_xp);
    cudaGetSymbolAddress((void**)&hbuf, g_hbuf);
    cudaGetSymbolAddress((void**)&whtf, g_whtf);
    cudaGetSymbolAddress((void**)&htf,  g_htf);
    float*    hA  = hbuf;
    float*    hB  = hbuf + BB * HH;
    uint32_t* hAt = htf;
    uint32_t* hBt = htf + BB * HH;

    // Pre-convert Wh (both layers) to tf32.
    {
        int n4 = 2 * 3 * HH * HH / 4;  // 1572864
        cvt_tf32_kernel<<<n4 / 256, 256>>>(Wh, whtf, n4);
    }

    dim3 xgrid(H3 / 128, (BB * TT) / 128);  // (24, 128)
    dim3 sgrid(HH / 32, BB / 32);           // (32, 4)

    for (int l = 0; l < 2; l++) {
        const float* cur = (l == 0) ? x : out;  // layer-1 input = layer-0 output
        xproj_kernel<<<xgrid, 256>>>(cur, Wx + (size_t)l * 3 * HH * HH,
                                     bx + (size_t)l * 3 * HH, xp);
        cudaMemcpyAsync(hA, h0 + (size_t)l * BB * HH, (size_t)BB * HH * sizeof(float),
                        cudaMemcpyDeviceToDevice);
        {
            int n4 = BB * HH / 4;  // 32768
            cvt_tf32_kernel<<<n4 / 256, 256>>>(h0 + (size_t)l * BB * HH, hAt, n4);
        }
        for (int t = 0; t < TT; t++) {
            const float*    hp  = (t & 1) ? hB  : hA;
            const uint32_t* hpt = (t & 1) ? hBt : hAt;
            float*          hn  = (t & 1) ? hA  : hB;
            uint32_t*       hnt = (t & 1) ? hAt : hBt;
            step2_kernel<<<sgrid, 256>>>(hp, hpt, whtf + (size_t)l * 3 * HH * HH,
                                         bh + (size_t)l * 3 * HH,
                                         xp + (size_t)t * BB * H3, hn, hnt, out, t);
        }
        // T=128 even -> final hidden ends up in hA
        cudaMemcpyAsync(hlast + (size_t)l * BB * HH, hA, (size_t)BB * HH * sizeof(float),
                        cudaMemcpyDeviceToDevice);
    }
}